// round 12
// baseline (speedup 1.0000x reference)
#include <cuda_runtime.h>
#include <cuda_fp16.h>

#define BB 8
#define NN 4096
#define EE 8190
#define VV 256
#define HH 128
#define TS 131072          // hash table slots (2^17)
#define TSM (TS - 1)
#define CAP 32             // adjacency capacity per node
#define NNODE (BB * NN)    // 32768
#define NBLK 128           // node-work blocks (256 nodes each)
#define FBLK 8             // finisher blocks
#define TTN 1024           // threads per node block
// smem: 64KB emb1 + 16KB dis + 4KB adjo4 + 4KB adji4 + 1KB ic + 1KB ty = 90KB
#define SMEM_NODE (VV * HH * 2 + NN * 4 + 256 * 16 + 256 * 16 + 256 * 4 + 256 * 4)

// -------- scratch (device globals; zero-initialized; cleaned per launch in-pipeline) --
__device__ unsigned int g_tab[TS];             // dedup hash table (key+1, 0=empty)
__device__ int          g_rowcnt[NNODE];       // unique out-degree
__device__ int          g_incnt[NNODE];        // unique in-degree
__device__ int          g_adjo[NNODE * CAP];   // out entries: j | (type_j<<12)
__device__ int          g_adji[NNODE * CAP];   // in entries: i
__device__ __half       g_emb1h[VV * HH];      // emb @ w1^T (fp16)
__device__ float        g_pooled[BB * HH];
__device__ unsigned int g_done;                // node-block completion counter

// ==== K1: single wave, 256 blocks x 512 thr.
//      Every thread: <=1 edge insert. Every warp: 1 emb1 warp-task. Overlapped. ====
__global__ void __launch_bounds__(512)
k_build(const int* __restrict__ type_ids, const int* __restrict__ edges,
        const float* __restrict__ emb, const float* __restrict__ w1) {
    const int tid  = threadIdx.x;
    const int lane = tid & 31;
    const int gtid = blockIdx.x * 512 + tid;
    if (gtid == 0) g_done = 0u;                     // reset for this replay

    // ---- edge dedup (set semantics) + adjacency build at insert time ----
    if (gtid < BB * EE) {
        int b = gtid / EE;
        int2 e = reinterpret_cast<const int2*>(edges)[gtid];
        unsigned key1 = (((unsigned)b << 24) | ((unsigned)e.x << 12) | (unsigned)e.y) + 1u;
        unsigned s = ((key1 * 0x9E3779B1u) >> 15) & TSM;
        while (true) {
            unsigned prev = atomicCAS(&g_tab[s], 0u, key1);
            if (prev == 0u) {                       // first inserter wins
                int ni = b * NN + e.x;
                int nj = b * NN + e.y;
                int oc = atomicAdd(&g_rowcnt[ni], 1);
                if (oc < CAP) g_adjo[ni * CAP + oc] = e.y | (type_ids[nj] << 12);
                int ic = atomicAdd(&g_incnt[nj], 1);
                if (ic < CAP) g_adji[nj * CAP + ic] = e.x;
                break;
            }
            if (prev == key1) break;                // duplicate: drop
            s = (s + 1) & TSM;
        }
    }

    // ---- emb1 = emb @ w1^T : warp-task = (v, 8 output cols); 4096 warps ----
    {
        int task = gtid >> 5;                       // 0..4095
        int v  = task >> 4;
        int c0 = (task & 15) * 8;
        const float* er = emb + v * HH;
        float ev[4];
        #pragma unroll
        for (int q = 0; q < 4; q++) ev[q] = er[lane + 32 * q];
        float p[8];
        #pragma unroll
        for (int cc = 0; cc < 8; cc++) {            // 32 independent coalesced LDGs
            const float* wr = w1 + (c0 + cc) * HH;
            float a = 0.f;
            #pragma unroll
            for (int q = 0; q < 4; q++) a = fmaf(ev[q], wr[lane + 32 * q], a);
            p[cc] = a;
        }
        __half res = __float2half(0.f);
        #pragma unroll
        for (int cc = 0; cc < 8; cc++) {
            float a = p[cc];
            #pragma unroll
            for (int off = 16; off; off >>= 1) a += __shfl_xor_sync(0xffffffffu, a, off);
            if (lane == cc) res = __float2half(a);
        }
        if (lane < 8) g_emb1h[v * HH + c0 + lane] = res;
    }
}

extern __shared__ char smem_raw[];

// ==== K2: blocks 0..127 node gather+pool (ALL loop inputs staged in smem);
//          blocks 128..135 finisher (spin -> GEMV+normalize -> scratch clean) ====
__global__ void __launch_bounds__(TTN, 1)
k_node(const int* __restrict__ type_ids, const float* __restrict__ b1,
       const float* __restrict__ w2, const float* __restrict__ b2,
       float* __restrict__ out) {
    const int tid  = threadIdx.x;
    const int lane = tid & 31;
    __half* s_e1   = reinterpret_cast<__half*>(smem_raw);                   // [VV*HH]
    float*  s_dis  = reinterpret_cast<float*>(smem_raw + VV * HH * 2);      // [NN]
    int4*   s_oe   = reinterpret_cast<int4*>(smem_raw + VV * HH * 2 + NN * 4);          // [256]
    int4*   s_ie   = reinterpret_cast<int4*>(smem_raw + VV * HH * 2 + NN * 4 + 4096);   // [256]
    int*    s_ic   = reinterpret_cast<int*>(smem_raw + VV * HH * 2 + NN * 4 + 8192);    // [256]
    int*    s_ty   = reinterpret_cast<int*>(smem_raw + VV * HH * 2 + NN * 4 + 9216);    // [256]

    if (blockIdx.x < NBLK) {
        const int blkStart = blockIdx.x * 256;      // 256 nodes per block
        const int b  = blkStart >> 12;
        const int bN = b << 12;

        // ---- cooperative staging (all independent, huge MLP) ----
        #pragma unroll
        for (int r = 0; r < 4; r++)                 // emb1: 64KB
            reinterpret_cast<uint4*>(s_e1)[tid + r * TTN] =
                reinterpret_cast<const uint4*>(g_emb1h)[tid + r * TTN];
        {                                           // dis for the whole batch: 16KB
            int4 rc = reinterpret_cast<const int4*>(g_rowcnt + bN)[tid];
            float4 d;
            d.x = rsqrtf(1.0f + (float)rc.x);
            d.y = rsqrtf(1.0f + (float)rc.y);
            d.z = rsqrtf(1.0f + (float)rc.z);
            d.w = rsqrtf(1.0f + (float)rc.w);
            reinterpret_cast<float4*>(s_dis)[tid] = d;
        }
        if (tid < 256) {                            // first-4 out/in entries + meta
            s_oe[tid] = *reinterpret_cast<const int4*>(&g_adjo[(blkStart + tid) * CAP]);
            s_ie[tid] = *reinterpret_cast<const int4*>(&g_adji[(blkStart + tid) * CAP]);
        } else if (tid < 320) {
            int u = tid - 256;
            reinterpret_cast<int4*>(s_ic)[u] = reinterpret_cast<const int4*>(g_incnt + blkStart)[u];
        } else if (tid < 384) {
            int u = tid - 320;
            reinterpret_cast<int4*>(s_ty)[u] = reinterpret_cast<const int4*>(type_ids + blkStart)[u];
        }
        __syncthreads();

        // ---- node loop: warp = 8 consecutive nodes; lane = 4 H-cols; all-LDS ----
        const int nbase = (tid >> 5) * 8;           // local node base (0..255)
        float4 b4 = reinterpret_cast<const float4*>(b1)[lane];
        float bias[4] = {b4.x, b4.y, b4.z, b4.w};
        float pac[4] = {0.f, 0.f, 0.f, 0.f};

        #pragma unroll 2
        for (int n = 0; n < 8; n++) {
            const int nl = nbase + n;               // local node idx (block slice)
            const int gl = blkStart - bN + nl;      // node idx within batch
            float di = s_dis[gl];
            float inv = 1.0f / (di * di);           // recover out-degree
            int o_ = __float2int_rn(inv) - 1;
            int i_ = s_ic[nl];
            int ty = s_ty[nl];
            int4 oe = s_oe[nl];
            int4 ie = s_ie[nl];
            float sacc[4];
            {
                uint2 r = reinterpret_cast<const uint2*>(s_e1 + ty * HH)[lane];
                float2 lo = __half22float2(*reinterpret_cast<__half2*>(&r.x));
                float2 hi = __half22float2(*reinterpret_cast<__half2*>(&r.y));
                sacc[0] = di * lo.x; sacc[1] = di * lo.y;
                sacc[2] = di * hi.x; sacc[3] = di * hi.y;
            }
            int vj[4] = {oe.x, oe.y, oe.z, oe.w};
            #pragma unroll
            for (int q = 0; q < 4; q++) {
                if (o_ > q) {
                    float dj = s_dis[vj[q] & 4095];
                    uint2 r = reinterpret_cast<const uint2*>(s_e1 + (vj[q] >> 12) * HH)[lane];
                    float2 lo = __half22float2(*reinterpret_cast<__half2*>(&r.x));
                    float2 hi = __half22float2(*reinterpret_cast<__half2*>(&r.y));
                    sacc[0] = fmaf(dj, lo.x, sacc[0]);
                    sacc[1] = fmaf(dj, lo.y, sacc[1]);
                    sacc[2] = fmaf(dj, hi.x, sacc[2]);
                    sacc[3] = fmaf(dj, hi.y, sacc[3]);
                }
            }
            if (o_ > 4) {                           // rare tail: global reads
                int dmax = min(o_, CAP);
                for (int d = 4; d < dmax; d++) {
                    int v = g_adjo[(blkStart + nl) * CAP + d];
                    float dj = s_dis[v & 4095];
                    uint2 r = reinterpret_cast<const uint2*>(s_e1 + (v >> 12) * HH)[lane];
                    float2 lo = __half22float2(*reinterpret_cast<__half2*>(&r.x));
                    float2 hi = __half22float2(*reinterpret_cast<__half2*>(&r.y));
                    sacc[0] = fmaf(dj, lo.x, sacc[0]);
                    sacc[1] = fmaf(dj, lo.y, sacc[1]);
                    sacc[2] = fmaf(dj, hi.x, sacc[2]);
                    sacc[3] = fmaf(dj, hi.y, sacc[3]);
                }
            }
            float ins = 0.f;
            if (i_ > 0) ins += s_dis[ie.x & 4095];
            if (i_ > 1) ins += s_dis[ie.y & 4095];
            if (i_ > 2) ins += s_dis[ie.z & 4095];
            if (i_ > 3) ins += s_dis[ie.w & 4095];
            if (i_ > 4) {
                int dmax = min(i_, CAP);
                for (int d = 4; d < dmax; d++)
                    ins += s_dis[g_adji[(blkStart + nl) * CAP + d] & 4095];
            }
            float cc = di * (di + ins);
            #pragma unroll
            for (int q = 0; q < 4; q++) {
                float hv = fmaxf(fmaf(di, sacc[q], bias[q]), 0.f);
                pac[q] = fmaf(cc, hv, pac[q]);
            }
        }
        // ---- block-level pooled reduction: smem then 128 global REDGs ----
        __syncthreads();
        float* s_pool = s_dis;                      // reuse
        if (tid < HH) s_pool[tid] = 0.f;
        __syncthreads();
        #pragma unroll
        for (int q = 0; q < 4; q++) atomicAdd(&s_pool[lane * 4 + q], pac[q]);
        __syncthreads();
        if (tid < HH) atomicAdd(&g_pooled[b * HH + tid], s_pool[tid]);
        __threadfence();
        __syncthreads();
        if (tid == 0) atomicAdd(&g_done, 1u);
        // ---- overlapped: clear this block's 4KB slice of the dedup table ----
        if (tid < 256)
            reinterpret_cast<uint4*>(g_tab)[blockIdx.x * 256 + tid] =
                make_uint4(0u, 0u, 0u, 0u);
    } else {
        // ---- finisher: one block per batch ----
        const int b = blockIdx.x - NBLK;
        if (tid == 0) {
            while (*((volatile unsigned*)&g_done) != NBLK) { }
        }
        __syncthreads();
        __threadfence();
        __shared__ float xs[HH];
        __shared__ float zsh[HH];
        __shared__ float nsum;
        if (tid < HH) {
            xs[tid] = g_pooled[b * HH + tid] * (1.0f / NN);
            g_pooled[b * HH + tid] = 0.f;           // clean for next replay
        }
        if (tid == 0) nsum = 0.f;
        __syncthreads();
        const int w = tid >> 5;                     // 32 warps -> 4 rows each
        float sqp = 0.f;
        for (int r = w * 4; r < w * 4 + 4; r++) {
            const float* wr = w2 + r * HH;
            float p = 0.f;
            #pragma unroll
            for (int q = 0; q < 4; q++) { int k = lane + q * 32; p = fmaf(wr[k], xs[k], p); }
            #pragma unroll
            for (int off = 16; off; off >>= 1) p += __shfl_xor_sync(0xffffffffu, p, off);
            if (lane == 0) {
                float z = p + b2[r];
                zsh[r] = z;
                sqp = fmaf(z, z, sqp);
            }
        }
        if (lane == 0) atomicAdd(&nsum, sqp);
        __syncthreads();
        if (tid < HH) {
            float nrm = fmaxf(sqrtf(nsum), 1e-12f);
            out[b * HH + tid] = zsh[tid] / nrm;
        }
        // clear degree counters for next replay (256KB over 8 blocks)
        uint4 z4 = make_uint4(0u, 0u, 0u, 0u);
        for (int i = b * TTN + tid; i < NNODE / 4; i += FBLK * TTN) {
            reinterpret_cast<uint4*>(g_rowcnt)[i] = z4;
            reinterpret_cast<uint4*>(g_incnt)[i] = z4;
        }
    }
}

extern "C" void kernel_launch(void* const* d_in, const int* in_sizes, int n_in,
                              void* d_out, int out_size) {
    const int*   type_ids = (const int*)d_in[0];
    const int*   edges    = (const int*)d_in[1];
    const float* emb      = (const float*)d_in[2];
    const float* w1       = (const float*)d_in[3];
    const float* b1       = (const float*)d_in[4];
    const float* w2       = (const float*)d_in[5];
    const float* b2       = (const float*)d_in[6];
    float* out = (float*)d_out;

    static int smem_set = 0;
    if (!smem_set) {
        cudaFuncSetAttribute(k_node, cudaFuncAttributeMaxDynamicSharedMemorySize, SMEM_NODE);
        smem_set = 1;
    }
    k_build<<<256, 512>>>(type_ids, edges, emb, w1);
    k_node<<<NBLK + FBLK, TTN, SMEM_NODE>>>(type_ids, b1, w2, b2, out);
}

// round 13
// speedup vs baseline: 1.0644x; 1.0644x over previous
#include <cuda_runtime.h>

#define BB 8
#define NN 4096
#define EE 8190
#define VV 256
#define HH 128
#define TS 131072          // hash table slots (2^17)
#define TSM (TS - 1)
#define CAP 32             // adjacency capacity per node
#define NNODE (BB * NN)    // 32768
#define GB 136             // total blocks (single wave; 1 block/SM via smem)
#define NBLK 128           // node-work blocks (256 nodes each)
#define TTN 1024           // threads per block
// smem: 128KB emb1 fp32 + 16KB dis + 4KB oe + 4KB ie + 1KB ic + 1KB ty = 154KB
#define SMEM_NODE (VV * HH * 4 + NN * 4 + 256 * 16 + 256 * 16 + 256 * 4 + 256 * 4)

// -------- scratch (device globals; zero-initialized; cleaned per launch in-pipeline) --
__device__ unsigned int g_tab[TS];             // dedup hash table (key+1, 0=empty)
__device__ int          g_rowcnt[NNODE];       // unique out-degree
__device__ int          g_incnt[NNODE];        // unique in-degree
__device__ int          g_adjo[NNODE * CAP];   // out entries: j | (type_j<<12)
__device__ int          g_adji[NNODE * CAP];   // in entries: i
__device__ float        g_emb1[VV * HH];       // emb @ w1^T (fp32)
__device__ float        g_pooled[BB * HH];
__device__ unsigned int g_done;                // node-block completion counter
__device__ unsigned int g_bar_cnt;
__device__ unsigned int g_bar_gen;

__device__ __forceinline__ void gridbar() {
    __syncthreads();
    if (threadIdx.x == 0) {
        __threadfence();
        unsigned gen = *((volatile unsigned*)&g_bar_gen);
        if (atomicAdd(&g_bar_cnt, 1u) == gridDim.x - 1) {
            *((volatile unsigned*)&g_bar_cnt) = 0u;
            __threadfence();
            *((volatile unsigned*)&g_bar_gen) = gen + 1u;
        } else {
            while (*((volatile unsigned*)&g_bar_gen) == gen) { }
            __threadfence();
        }
    }
    __syncthreads();
}

extern __shared__ char smem_raw[];

__global__ void __launch_bounds__(TTN, 1)
gnn(const int* __restrict__ type_ids, const int* __restrict__ edges,
    const float* __restrict__ emb, const float* __restrict__ w1,
    const float* __restrict__ b1, const float* __restrict__ w2,
    const float* __restrict__ b2, float* __restrict__ out) {
    const int tid  = threadIdx.x;
    const int lane = tid & 31;
    const int gtid = blockIdx.x * TTN + tid;
    const int gw   = gtid >> 5;                 // 0..4351

    float* s_e1  = reinterpret_cast<float*>(smem_raw);                        // [VV*HH]
    float* s_dis = reinterpret_cast<float*>(smem_raw + VV * HH * 4);          // [NN]
    int4*  s_oe  = reinterpret_cast<int4*>(smem_raw + VV * HH * 4 + NN * 4);          // [256]
    int4*  s_ie  = reinterpret_cast<int4*>(smem_raw + VV * HH * 4 + NN * 4 + 4096);   // [256]
    int*   s_ic  = reinterpret_cast<int*>(smem_raw + VV * HH * 4 + NN * 4 + 8192);    // [256]
    int*   s_ty  = reinterpret_cast<int*>(smem_raw + VV * HH * 4 + NN * 4 + 9216);    // [256]

    // ================= Phase A: DISJOINT warp roles =================
    if (gtid == 0) g_done = 0u;                 // reset for this replay
    if (gw < 2048) {
        // ---- emb1 = emb @ w1^T : warp-task = (v, 16 output cols) ----
        int v  = gw >> 3;
        int c0 = (gw & 7) * 16;
        const float* er = emb + v * HH;
        float ev[4];
        #pragma unroll
        for (int q = 0; q < 4; q++) ev[q] = er[lane + 32 * q];
        float p[16];
        #pragma unroll
        for (int cc = 0; cc < 16; cc++) {       // 64 independent coalesced LDGs
            const float* wr = w1 + (c0 + cc) * HH;
            float a = 0.f;
            #pragma unroll
            for (int q = 0; q < 4; q++) a = fmaf(ev[q], wr[lane + 32 * q], a);
            p[cc] = a;
        }
        float res = 0.f;
        #pragma unroll
        for (int cc = 0; cc < 16; cc++) {
            float a = p[cc];
            #pragma unroll
            for (int off = 16; off; off >>= 1) a += __shfl_xor_sync(0xffffffffu, a, off);
            if (lane == cc) res = a;
        }
        if (lane < 16) g_emb1[v * HH + c0 + lane] = res;
    } else if (gw < 4096) {
        // ---- edge dedup (set semantics) + adjacency build: one edge per lane ----
        int t = (gw - 2048) * 32 + lane;
        if (t < BB * EE) {
            int b = t / EE;
            int2 e = reinterpret_cast<const int2*>(edges)[t];
            unsigned key1 = (((unsigned)b << 24) | ((unsigned)e.x << 12) | (unsigned)e.y) + 1u;
            unsigned s = ((key1 * 0x9E3779B1u) >> 15) & TSM;
            while (true) {
                unsigned prev = atomicCAS(&g_tab[s], 0u, key1);
                if (prev == 0u) {               // first inserter wins
                    int ni = b * NN + e.x;
                    int nj = b * NN + e.y;
                    int oc = atomicAdd(&g_rowcnt[ni], 1);
                    if (oc < CAP) g_adjo[ni * CAP + oc] = e.y | (type_ids[nj] << 12);
                    int ic = atomicAdd(&g_incnt[nj], 1);
                    if (ic < CAP) g_adji[nj * CAP + ic] = e.x;
                    break;
                }
                if (prev == key1) break;        // duplicate: drop
                s = (s + 1) & TSM;
            }
        }
    }
    gridbar();

    // ================= Phase B: node gather+pool / finisher =================
    if (blockIdx.x < NBLK) {
        const int blkStart = blockIdx.x * 256;  // 256 nodes per block
        const int b  = blkStart >> 12;
        const int bN = b << 12;

        // ---- cooperative staging (independent, huge MLP) ----
        #pragma unroll
        for (int r = 0; r < 8; r++)             // emb1: 128KB fp32
            reinterpret_cast<uint4*>(s_e1)[tid + r * TTN] =
                reinterpret_cast<const uint4*>(g_emb1)[tid + r * TTN];
        {                                       // dis for the whole batch: 16KB
            int4 rc = reinterpret_cast<const int4*>(g_rowcnt + bN)[tid];
            float4 d;
            d.x = rsqrtf(1.0f + (float)rc.x);
            d.y = rsqrtf(1.0f + (float)rc.y);
            d.z = rsqrtf(1.0f + (float)rc.z);
            d.w = rsqrtf(1.0f + (float)rc.w);
            reinterpret_cast<float4*>(s_dis)[tid] = d;
        }
        if (tid < 256) {                        // first-4 out/in entries + meta
            s_oe[tid] = *reinterpret_cast<const int4*>(&g_adjo[(blkStart + tid) * CAP]);
            s_ie[tid] = *reinterpret_cast<const int4*>(&g_adji[(blkStart + tid) * CAP]);
        } else if (tid < 320) {
            int u = tid - 256;
            reinterpret_cast<int4*>(s_ic)[u] = reinterpret_cast<const int4*>(g_incnt + blkStart)[u];
        } else if (tid < 384) {
            int u = tid - 320;
            reinterpret_cast<int4*>(s_ty)[u] = reinterpret_cast<const int4*>(type_ids + blkStart)[u];
        }
        __syncthreads();

        // ---- node loop: warp = 8 consecutive nodes; lane = 4 H-cols; all-LDS ----
        const int nbase = (tid >> 5) * 8;
        float4 b4 = reinterpret_cast<const float4*>(b1)[lane];
        float bias[4] = {b4.x, b4.y, b4.z, b4.w};
        float pac[4] = {0.f, 0.f, 0.f, 0.f};

        #pragma unroll 2
        for (int n = 0; n < 8; n++) {
            const int nl = nbase + n;
            const int gl = blkStart - bN + nl;
            float di = s_dis[gl];
            float inv = 1.0f / (di * di);       // recover out-degree
            int o_ = __float2int_rn(inv) - 1;
            int i_ = s_ic[nl];
            int ty = s_ty[nl];
            int4 oe = s_oe[nl];
            int4 ie = s_ie[nl];
            float sacc[4];
            {
                float4 r = reinterpret_cast<const float4*>(s_e1 + ty * HH)[lane];
                sacc[0] = di * r.x; sacc[1] = di * r.y;
                sacc[2] = di * r.z; sacc[3] = di * r.w;
            }
            int vj[4] = {oe.x, oe.y, oe.z, oe.w};
            #pragma unroll
            for (int q = 0; q < 4; q++) {
                if (o_ > q) {
                    float dj = s_dis[vj[q] & 4095];
                    float4 r = reinterpret_cast<const float4*>(s_e1 + (vj[q] >> 12) * HH)[lane];
                    sacc[0] = fmaf(dj, r.x, sacc[0]);
                    sacc[1] = fmaf(dj, r.y, sacc[1]);
                    sacc[2] = fmaf(dj, r.z, sacc[2]);
                    sacc[3] = fmaf(dj, r.w, sacc[3]);
                }
            }
            if (o_ > 4) {                       // rare tail: global adjacency reads
                int dmax = min(o_, CAP);
                for (int d = 4; d < dmax; d++) {
                    int v = g_adjo[(blkStart + nl) * CAP + d];
                    float dj = s_dis[v & 4095];
                    float4 r = reinterpret_cast<const float4*>(s_e1 + (v >> 12) * HH)[lane];
                    sacc[0] = fmaf(dj, r.x, sacc[0]);
                    sacc[1] = fmaf(dj, r.y, sacc[1]);
                    sacc[2] = fmaf(dj, r.z, sacc[2]);
                    sacc[3] = fmaf(dj, r.w, sacc[3]);
                }
            }
            float ins = 0.f;
            if (i_ > 0) ins += s_dis[ie.x & 4095];
            if (i_ > 1) ins += s_dis[ie.y & 4095];
            if (i_ > 2) ins += s_dis[ie.z & 4095];
            if (i_ > 3) ins += s_dis[ie.w & 4095];
            if (i_ > 4) {
                int dmax = min(i_, CAP);
                for (int d = 4; d < dmax; d++)
                    ins += s_dis[g_adji[(blkStart + nl) * CAP + d] & 4095];
            }
            float cc = di * (di + ins);
            #pragma unroll
            for (int q = 0; q < 4; q++) {
                float hv = fmaxf(fmaf(di, sacc[q], bias[q]), 0.f);
                pac[q] = fmaf(cc, hv, pac[q]);
            }
        }
        // ---- block-level pooled reduction: smem then 128 global REDGs ----
        __syncthreads();
        float* s_pool = s_dis;                  // reuse
        if (tid < HH) s_pool[tid] = 0.f;
        __syncthreads();
        #pragma unroll
        for (int q = 0; q < 4; q++) atomicAdd(&s_pool[lane * 4 + q], pac[q]);
        __syncthreads();
        if (tid < HH) atomicAdd(&g_pooled[b * HH + tid], s_pool[tid]);
        __threadfence();
        __syncthreads();
        if (tid == 0) atomicAdd(&g_done, 1u);
        // ---- overlapped: clear this block's 4KB slice of the dedup table ----
        if (tid < 256)
            reinterpret_cast<uint4*>(g_tab)[blockIdx.x * 256 + tid] =
                make_uint4(0u, 0u, 0u, 0u);
    } else {
        // ---- finisher: one block per batch; spin until all node blocks done ----
        const int b = blockIdx.x - NBLK;
        if (tid == 0) {
            while (*((volatile unsigned*)&g_done) != NBLK) { }
        }
        __syncthreads();
        __threadfence();
        __shared__ float xs[HH];
        __shared__ float zsh[HH];
        __shared__ float nsum;
        if (tid < HH) {
            xs[tid] = g_pooled[b * HH + tid] * (1.0f / NN);
            g_pooled[b * HH + tid] = 0.f;       // clean for next replay
        }
        if (tid == 0) nsum = 0.f;
        __syncthreads();
        const int w = tid >> 5;                 // 32 warps -> 4 rows each
        float sqp = 0.f;
        for (int r = w * 4; r < w * 4 + 4; r++) {
            const float* wr = w2 + r * HH;
            float p = 0.f;
            #pragma unroll
            for (int q = 0; q < 4; q++) { int k = lane + q * 32; p = fmaf(wr[k], xs[k], p); }
            #pragma unroll
            for (int off = 16; off; off >>= 1) p += __shfl_xor_sync(0xffffffffu, p, off);
            if (lane == 0) {
                float z = p + b2[r];
                zsh[r] = z;
                sqp = fmaf(z, z, sqp);
            }
        }
        if (lane == 0) atomicAdd(&nsum, sqp);
        __syncthreads();
        if (tid < HH) {
            float nrm = fmaxf(sqrtf(nsum), 1e-12f);
            out[b * HH + tid] = zsh[tid] / nrm;
        }
        // clear degree counters for next replay (256KB over 8 blocks)
        uint4 z4 = make_uint4(0u, 0u, 0u, 0u);
        for (int i = b * TTN + tid; i < NNODE / 4; i += 8 * TTN) {
            reinterpret_cast<uint4*>(g_rowcnt)[i] = z4;
            reinterpret_cast<uint4*>(g_incnt)[i] = z4;
        }
    }
}

extern "C" void kernel_launch(void* const* d_in, const int* in_sizes, int n_in,
                              void* d_out, int out_size) {
    const int*   type_ids = (const int*)d_in[0];
    const int*   edges    = (const int*)d_in[1];
    const float* emb      = (const float*)d_in[2];
    const float* w1       = (const float*)d_in[3];
    const float* b1       = (const float*)d_in[4];
    const float* w2       = (const float*)d_in[5];
    const float* b2       = (const float*)d_in[6];
    float* out = (float*)d_out;

    static int smem_set = 0;
    if (!smem_set) {
        cudaFuncSetAttribute(gnn, cudaFuncAttributeMaxDynamicSharedMemorySize, SMEM_NODE);
        smem_set = 1;
    }
    gnn<<<GB, TTN, SMEM_NODE>>>(type_ids, edges, emb, w1, b1, w2, b2, out);
}

// round 14
// speedup vs baseline: 1.4016x; 1.3168x over previous
#include <cuda_runtime.h>
#include <cuda_fp16.h>

#define BB 8
#define NN 4096
#define EE 8190
#define VV 256
#define HH 128
#define TS 131072          // hash table slots (2^17)
#define TSM (TS - 1)
#define CAP 32             // adjacency capacity per node
#define NNODE (BB * NN)    // 32768
#define NBLK 128           // node-work blocks (256 nodes each)
#define FBLK 8             // finisher blocks
#define TTN 1024           // threads per node block
// smem: 64KB emb1 fp16 + 16KB dis + 4KB oe + 4KB ie + 1KB ic + 1KB ty + 16KB wsum = 106KB
#define SMEM_NODE (VV * HH * 2 + NN * 4 + 256 * 16 + 256 * 16 + 256 * 4 + 256 * 4 + 32 * HH * 4)

// -------- scratch (device globals; zero-initialized; cleaned per launch in-pipeline) --
__device__ unsigned int g_tab[TS];             // dedup hash table (key+1, 0=empty)
__device__ int          g_rowcnt[NNODE];       // unique out-degree
__device__ int          g_incnt[NNODE];        // unique in-degree
__device__ int          g_adjo[NNODE * CAP];   // out entries: j | (type_j<<12)
__device__ int          g_adji[NNODE * CAP];   // in entries: i
__device__ __half       g_emb1h[VV * HH];      // emb @ w1^T (fp16)
__device__ float        g_pooled[BB * HH];
__device__ unsigned int g_done;                // node-block completion counter

// ==== K1: single wave, 256 blocks x 512 thr, DISJOINT block roles.
//      Blocks 0..127: emb1 warp-tasks. Blocks 128..255: one edge insert per thread. ====
__global__ void __launch_bounds__(512)
k_build(const int* __restrict__ type_ids, const int* __restrict__ edges,
        const float* __restrict__ emb, const float* __restrict__ w1) {
    const int tid  = threadIdx.x;
    const int lane = tid & 31;
    if (blockIdx.x == 0 && tid == 0) g_done = 0u;   // reset for this replay
    if (blockIdx.x < 128) {
        // ---- emb1 = emb @ w1^T : warp-task = (v, 16 output cols); 2048 warps ----
        int task = blockIdx.x * 16 + (tid >> 5);    // 0..2047
        int v  = task >> 3;
        int c0 = (task & 7) * 16;
        const float* er = emb + v * HH;
        float ev[4];
        #pragma unroll
        for (int q = 0; q < 4; q++) ev[q] = er[lane + 32 * q];
        float p[16];
        #pragma unroll
        for (int cc = 0; cc < 16; cc++) {           // 64 independent coalesced LDGs
            const float* wr = w1 + (c0 + cc) * HH;
            float a = 0.f;
            #pragma unroll
            for (int q = 0; q < 4; q++) a = fmaf(ev[q], wr[lane + 32 * q], a);
            p[cc] = a;
        }
        __half res = __float2half(0.f);
        #pragma unroll
        for (int cc = 0; cc < 16; cc++) {           // 16 independent shfl chains
            float a = p[cc];
            #pragma unroll
            for (int off = 16; off; off >>= 1) a += __shfl_xor_sync(0xffffffffu, a, off);
            if (lane == cc) res = __float2half(a);
        }
        if (lane < 16) g_emb1h[v * HH + c0 + lane] = res;
    } else {
        // ---- edge dedup (set semantics) + adjacency build: one edge per thread ----
        int t = (blockIdx.x - 128) * 512 + tid;
        if (t >= BB * EE) return;
        int b = t / EE;
        int2 e = reinterpret_cast<const int2*>(edges)[t];
        unsigned key1 = (((unsigned)b << 24) | ((unsigned)e.x << 12) | (unsigned)e.y) + 1u;
        unsigned s = ((key1 * 0x9E3779B1u) >> 15) & TSM;
        while (true) {
            unsigned prev = atomicCAS(&g_tab[s], 0u, key1);
            if (prev == 0u) {                       // first inserter wins
                int ni = b * NN + e.x;
                int nj = b * NN + e.y;
                int oc = atomicAdd(&g_rowcnt[ni], 1);
                if (oc < CAP) g_adjo[ni * CAP + oc] = e.y | (type_ids[nj] << 12);
                int ic = atomicAdd(&g_incnt[nj], 1);
                if (ic < CAP) g_adji[nj * CAP + ic] = e.x;
                break;
            }
            if (prev == key1) break;                // duplicate: drop
            s = (s + 1) & TSM;
        }
    }
}

extern __shared__ char smem_raw[];

// ==== K2: blocks 0..127 node gather+pool (ALL loop inputs staged in smem);
//          blocks 128..135 finisher (spin -> GEMV+normalize -> scratch clean) ====
__global__ void __launch_bounds__(TTN, 1)
k_node(const int* __restrict__ type_ids, const float* __restrict__ b1,
       const float* __restrict__ w2, const float* __restrict__ b2,
       float* __restrict__ out) {
    const int tid  = threadIdx.x;
    const int lane = tid & 31;
    __half* s_e1   = reinterpret_cast<__half*>(smem_raw);                   // [VV*HH]
    float*  s_dis  = reinterpret_cast<float*>(smem_raw + VV * HH * 2);      // [NN]
    int4*   s_oe   = reinterpret_cast<int4*>(smem_raw + VV * HH * 2 + NN * 4);          // [256]
    int4*   s_ie   = reinterpret_cast<int4*>(smem_raw + VV * HH * 2 + NN * 4 + 4096);   // [256]
    int*    s_ic   = reinterpret_cast<int*>(smem_raw + VV * HH * 2 + NN * 4 + 8192);    // [256]
    int*    s_ty   = reinterpret_cast<int*>(smem_raw + VV * HH * 2 + NN * 4 + 9216);    // [256]
    float*  s_wsum = reinterpret_cast<float*>(smem_raw + VV * HH * 2 + NN * 4 + 10240); // [32*HH]

    if (blockIdx.x < NBLK) {
        const int blkStart = blockIdx.x * 256;      // 256 nodes per block
        const int b  = blkStart >> 12;
        const int bN = b << 12;

        // ---- cooperative staging (all independent, huge MLP) ----
        #pragma unroll
        for (int r = 0; r < 4; r++)                 // emb1: 64KB
            reinterpret_cast<uint4*>(s_e1)[tid + r * TTN] =
                reinterpret_cast<const uint4*>(g_emb1h)[tid + r * TTN];
        {                                           // dis for the whole batch: 16KB
            int4 rc = reinterpret_cast<const int4*>(g_rowcnt + bN)[tid];
            float4 d;
            d.x = rsqrtf(1.0f + (float)rc.x);
            d.y = rsqrtf(1.0f + (float)rc.y);
            d.z = rsqrtf(1.0f + (float)rc.z);
            d.w = rsqrtf(1.0f + (float)rc.w);
            reinterpret_cast<float4*>(s_dis)[tid] = d;
        }
        if (tid < 256) {                            // first-4 out/in entries + meta
            s_oe[tid] = *reinterpret_cast<const int4*>(&g_adjo[(blkStart + tid) * CAP]);
            s_ie[tid] = *reinterpret_cast<const int4*>(&g_adji[(blkStart + tid) * CAP]);
        } else if (tid < 320) {
            int u = tid - 256;
            reinterpret_cast<int4*>(s_ic)[u] = reinterpret_cast<const int4*>(g_incnt + blkStart)[u];
        } else if (tid < 384) {
            int u = tid - 320;
            reinterpret_cast<int4*>(s_ty)[u] = reinterpret_cast<const int4*>(type_ids + blkStart)[u];
        }
        __syncthreads();

        // ---- node loop: warp = 8 consecutive nodes; lane = 4 H-cols; all-LDS ----
        const int nbase = (tid >> 5) * 8;           // local node base (0..255)
        float4 b4 = reinterpret_cast<const float4*>(b1)[lane];
        float bias[4] = {b4.x, b4.y, b4.z, b4.w};
        float pac[4] = {0.f, 0.f, 0.f, 0.f};

        #pragma unroll 2
        for (int n = 0; n < 8; n++) {
            const int nl = nbase + n;               // local node idx (block slice)
            const int gl = blkStart - bN + nl;      // node idx within batch
            float di = s_dis[gl];
            float inv = 1.0f / (di * di);           // recover out-degree
            int o_ = __float2int_rn(inv) - 1;
            int i_ = s_ic[nl];
            int ty = s_ty[nl];
            int4 oe = s_oe[nl];
            int4 ie = s_ie[nl];
            float sacc[4];
            {
                uint2 r = reinterpret_cast<const uint2*>(s_e1 + ty * HH)[lane];
                float2 lo = __half22float2(*reinterpret_cast<__half2*>(&r.x));
                float2 hi = __half22float2(*reinterpret_cast<__half2*>(&r.y));
                sacc[0] = di * lo.x; sacc[1] = di * lo.y;
                sacc[2] = di * hi.x; sacc[3] = di * hi.y;
            }
            int vj[4] = {oe.x, oe.y, oe.z, oe.w};
            #pragma unroll
            for (int q = 0; q < 4; q++) {
                if (o_ > q) {
                    float dj = s_dis[vj[q] & 4095];
                    uint2 r = reinterpret_cast<const uint2*>(s_e1 + (vj[q] >> 12) * HH)[lane];
                    float2 lo = __half22float2(*reinterpret_cast<__half2*>(&r.x));
                    float2 hi = __half22float2(*reinterpret_cast<__half2*>(&r.y));
                    sacc[0] = fmaf(dj, lo.x, sacc[0]);
                    sacc[1] = fmaf(dj, lo.y, sacc[1]);
                    sacc[2] = fmaf(dj, hi.x, sacc[2]);
                    sacc[3] = fmaf(dj, hi.y, sacc[3]);
                }
            }
            if (o_ > 4) {                           // rare tail: global reads
                int dmax = min(o_, CAP);
                for (int d = 4; d < dmax; d++) {
                    int v = g_adjo[(blkStart + nl) * CAP + d];
                    float dj = s_dis[v & 4095];
                    uint2 r = reinterpret_cast<const uint2*>(s_e1 + (v >> 12) * HH)[lane];
                    float2 lo = __half22float2(*reinterpret_cast<__half2*>(&r.x));
                    float2 hi = __half22float2(*reinterpret_cast<__half2*>(&r.y));
                    sacc[0] = fmaf(dj, lo.x, sacc[0]);
                    sacc[1] = fmaf(dj, lo.y, sacc[1]);
                    sacc[2] = fmaf(dj, hi.x, sacc[2]);
                    sacc[3] = fmaf(dj, hi.y, sacc[3]);
                }
            }
            float ins = 0.f;
            if (i_ > 0) ins += s_dis[ie.x & 4095];
            if (i_ > 1) ins += s_dis[ie.y & 4095];
            if (i_ > 2) ins += s_dis[ie.z & 4095];
            if (i_ > 3) ins += s_dis[ie.w & 4095];
            if (i_ > 4) {
                int dmax = min(i_, CAP);
                for (int d = 4; d < dmax; d++)
                    ins += s_dis[g_adji[(blkStart + nl) * CAP + d] & 4095];
            }
            float cc = di * (di + ins);
            #pragma unroll
            for (int q = 0; q < 4; q++) {
                float hv = fmaxf(fmaf(di, sacc[q], bias[q]), 0.f);
                pac[q] = fmaf(cc, hv, pac[q]);
            }
        }
        // ---- pooled reduction: conflict-free per-warp stores + tree sum ----
        __syncthreads();
        {
            const int w = tid >> 5;
            #pragma unroll
            for (int q = 0; q < 4; q++) s_wsum[w * HH + lane * 4 + q] = pac[q];
        }
        __syncthreads();
        if (tid < HH) {
            float acc = 0.f;
            #pragma unroll 8
            for (int w = 0; w < 32; w++) acc += s_wsum[w * HH + tid];
            atomicAdd(&g_pooled[b * HH + tid], acc);
        }
        __threadfence();
        __syncthreads();
        if (tid == 0) atomicAdd(&g_done, 1u);
        // ---- overlapped: clear this block's 4KB slice of the dedup table ----
        if (tid < 256)
            reinterpret_cast<uint4*>(g_tab)[blockIdx.x * 256 + tid] =
                make_uint4(0u, 0u, 0u, 0u);
    } else {
        // ---- finisher: one block per batch ----
        const int b = blockIdx.x - NBLK;
        if (tid == 0) {
            while (*((volatile unsigned*)&g_done) != NBLK) { }
        }
        __syncthreads();
        __threadfence();
        __shared__ float xs[HH];
        __shared__ float zsh[HH];
        __shared__ float nsum;
        if (tid < HH) {
            xs[tid] = g_pooled[b * HH + tid] * (1.0f / NN);
            g_pooled[b * HH + tid] = 0.f;           // clean for next replay
        }
        if (tid == 0) nsum = 0.f;
        __syncthreads();
        const int w = tid >> 5;                     // 32 warps -> 4 rows each
        float sqp = 0.f;
        for (int r = w * 4; r < w * 4 + 4; r++) {
            const float* wr = w2 + r * HH;
            float p = 0.f;
            #pragma unroll
            for (int q = 0; q < 4; q++) { int k = lane + q * 32; p = fmaf(wr[k], xs[k], p); }
            #pragma unroll
            for (int off = 16; off; off >>= 1) p += __shfl_xor_sync(0xffffffffu, p, off);
            if (lane == 0) {
                float z = p + b2[r];
                zsh[r] = z;
                sqp = fmaf(z, z, sqp);
            }
        }
        if (lane == 0) atomicAdd(&nsum, sqp);
        __syncthreads();
        if (tid < HH) {
            float nrm = fmaxf(sqrtf(nsum), 1e-12f);
            out[b * HH + tid] = zsh[tid] / nrm;
        }
        // clear degree counters for next replay (256KB over 8 blocks)
        uint4 z4 = make_uint4(0u, 0u, 0u, 0u);
        for (int i = b * TTN + tid; i < NNODE / 4; i += FBLK * TTN) {
            reinterpret_cast<uint4*>(g_rowcnt)[i] = z4;
            reinterpret_cast<uint4*>(g_incnt)[i] = z4;
        }
    }
}

extern "C" void kernel_launch(void* const* d_in, const int* in_sizes, int n_in,
                              void* d_out, int out_size) {
    const int*   type_ids = (const int*)d_in[0];
    const int*   edges    = (const int*)d_in[1];
    const float* emb      = (const float*)d_in[2];
    const float* w1       = (const float*)d_in[3];
    const float* b1       = (const float*)d_in[4];
    const float* w2       = (const float*)d_in[5];
    const float* b2       = (const float*)d_in[6];
    float* out = (float*)d_out;

    static int smem_set = 0;
    if (!smem_set) {
        cudaFuncSetAttribute(k_node, cudaFuncAttributeMaxDynamicSharedMemorySize, SMEM_NODE);
        smem_set = 1;
    }
    k_build<<<256, 512>>>(type_ids, edges, emb, w1);
    k_node<<<NBLK + FBLK, TTN, SMEM_NODE>>>(type_ids, b1, w2, b2, out);
}